// round 5
// baseline (speedup 1.0000x reference)
#include <cuda_runtime.h>
#include <cuda_fp16.h>
#include <stdint.h>
#include <math.h>

// Problem constants (fixed by dataset)
#define Bsz  8
#define Qlen 2048
#define Klen 2048
#define Hdim 128
#define BM   64          // queries per CTA
#define BN   64          // keys per tile
#define NT   128         // 4 warps
#define NTILE (Klen / BN)

#define KTOT (Bsz * Klen * Hdim)   // 2,097,152 elements

// Pre-split history scratch (fp16 hi + residual lo), row-major [b][key][h]
__device__ __align__(16) __half g_khi[KTOT];
__device__ __align__(16) __half g_klo[KTOT];

// smem tile: 64 rows x 128 fp16 = 16KB (hi) + 16KB (lo); double buffered = 64KB
#define TILE_HI_BYTES 16384
#define TILE_BYTES    32768
#define SMEM_BYTES    (2 * TILE_BYTES)

__device__ __forceinline__ uint32_t smem_u32(const void* p) {
    uint32_t a;
    asm("{ .reg .u64 t; cvta.to.shared.u64 t, %1; cvt.u32.u64 %0, t; }" : "=r"(a) : "l"(p));
    return a;
}
__device__ __forceinline__ uint32_t h2u(__half2 h) { return *reinterpret_cast<uint32_t*>(&h); }

// fp32 pair -> fp16 hi + fp16 residual(lo), packed half2
__device__ __forceinline__ void split_h2(float x, float y, uint32_t& hi, uint32_t& lo) {
    __half2 h = __floats2half2_rn(x, y);
    float rx = x - __half2float(__low2half(h));
    float ry = y - __half2float(__high2half(h));
    __half2 l = __floats2half2_rn(rx, ry);
    hi = h2u(h); lo = h2u(l);
}

// XOR-swizzled tile offset: row in [0,64), bytecol in [0,256); 16B chunk ^ row&7,
// preserving the 128B half bit (chunk bit 3).
__device__ __forceinline__ uint32_t swz2(int row, int bytecol) {
    int ch = bytecol >> 4;
    int chs = (ch & 8) | ((ch ^ row) & 7);
    return (uint32_t)(row * 256 + (chs << 4));
}

__device__ __forceinline__ void cpa16(uint32_t dst, const void* src) {
    asm volatile("cp.async.cg.shared.global [%0], [%1], 16;" :: "r"(dst), "l"(src));
}
#define CP_COMMIT() asm volatile("cp.async.commit_group;" ::: "memory")
#define CP_WAIT0()  asm volatile("cp.async.wait_group 0;" ::: "memory")

__device__ __forceinline__ void ldsm_x4(uint32_t& r0, uint32_t& r1, uint32_t& r2, uint32_t& r3,
                                        uint32_t addr) {
    asm volatile("ldmatrix.sync.aligned.m8n8.x4.shared.b16 {%0,%1,%2,%3}, [%4];"
                 : "=r"(r0), "=r"(r1), "=r"(r2), "=r"(r3) : "r"(addr));
}
__device__ __forceinline__ void ldsm_x4_t(uint32_t& r0, uint32_t& r1, uint32_t& r2, uint32_t& r3,
                                          uint32_t addr) {
    asm volatile("ldmatrix.sync.aligned.m8n8.x4.trans.shared.b16 {%0,%1,%2,%3}, [%4];"
                 : "=r"(r0), "=r"(r1), "=r"(r2), "=r"(r3) : "r"(addr));
}
// D(16x8,f32) += A(16x16,f16) * B(16x8,f16)
__device__ __forceinline__ void mma16816(float* d, const uint32_t* a, uint32_t b0, uint32_t b1) {
    asm volatile("mma.sync.aligned.m16n8k16.row.col.f32.f16.f16.f32 "
                 "{%0,%1,%2,%3}, {%4,%5,%6,%7}, {%8,%9}, {%0,%1,%2,%3};"
                 : "+f"(d[0]), "+f"(d[1]), "+f"(d[2]), "+f"(d[3])
                 : "r"(a[0]), "r"(a[1]), "r"(a[2]), "r"(a[3]), "r"(b0), "r"(b1));
}

// ---------------- Pre-pass: split history fp32 -> fp16 hi/lo ----------------
__global__ __launch_bounds__(256)
void prep_split(const float* __restrict__ history)
{
    const size_t i = ((size_t)blockIdx.x * 256 + threadIdx.x) * 8;
    float4 a = *(const float4*)(history + i);
    float4 b = *(const float4*)(history + i + 4);
    uint32_t h[4], l[4];
    split_h2(a.x, a.y, h[0], l[0]);
    split_h2(a.z, a.w, h[1], l[1]);
    split_h2(b.x, b.y, h[2], l[2]);
    split_h2(b.z, b.w, h[3], l[3]);
    *(uint4*)(g_khi + i) = make_uint4(h[0], h[1], h[2], h[3]);
    *(uint4*)(g_klo + i) = make_uint4(l[0], l[1], l[2], l[3]);
}

// ---------------- Main attention kernel ----------------
__global__ __launch_bounds__(NT, 2)
void attn_hmma(const float* __restrict__ out_state,
               float* __restrict__ out)
{
    extern __shared__ __align__(16) char smb[];
    const uint32_t s_base = smem_u32(smb);

    const int t    = threadIdx.x;
    const int wm   = t >> 5;          // warp id = query-row group
    const int lane = t & 31;
    const int g    = lane >> 2;       // row within fragment group (0..7)
    const int tc   = lane & 3;        // col pair within group
    const int q0   = blockIdx.x * BM;
    const int b    = blockIdx.y;

    const float*  q_g  = out_state + (size_t)b * Qlen * Hdim;
    const __half* khiB = g_khi + (size_t)b * Klen * Hdim;
    const __half* kloB = g_klo + (size_t)b * Klen * Hdim;
    float*        o_g  = out + (size_t)b * Qlen * Hdim;

    // ---- Q A-fragments in registers: rows wm*16+g and +8, split fp16 hi/lo ----
    uint32_t qhi[8][4], qlo[8][4];
    {
        const float* qb = q_g + (size_t)(q0 + wm * 16 + g) * Hdim;
        #pragma unroll
        for (int kk = 0; kk < 8; ++kk) {
            const int h0 = kk * 16 + tc * 2;
            float2 x00 = *(const float2*)(qb + h0);
            float2 x10 = *(const float2*)(qb + 8 * Hdim + h0);
            float2 x01 = *(const float2*)(qb + h0 + 8);
            float2 x11 = *(const float2*)(qb + 8 * Hdim + h0 + 8);
            x00.x = tanhf(x00.x); x00.y = tanhf(x00.y);
            x10.x = tanhf(x10.x); x10.y = tanhf(x10.y);
            x01.x = tanhf(x01.x); x01.y = tanhf(x01.y);
            x11.x = tanhf(x11.x); x11.y = tanhf(x11.y);
            split_h2(x00.x, x00.y, qhi[kk][0], qlo[kk][0]);
            split_h2(x10.x, x10.y, qhi[kk][1], qlo[kk][1]);
            split_h2(x01.x, x01.y, qhi[kk][2], qlo[kk][2]);
            split_h2(x11.x, x11.y, qhi[kk][3], qlo[kk][3]);
        }
    }

    // O accumulator: 16 h-tiles x 4 f32 (rows g, g+8)
    float o[16][4];
    #pragma unroll
    for (int n = 0; n < 16; ++n)
        #pragma unroll
        for (int j = 0; j < 4; ++j) o[n][j] = 0.f;

    float m0 = -INFINITY, m1 = -INFINITY, l0 = 0.f, l1 = 0.f;

    // ---- Prefetch tile 0 into buffer 0 ----
    {
        #pragma unroll
        for (int j = 0; j < 8; ++j) {
            const int idx = j * NT + t;        // 0..1023
            const int row = idx >> 4;
            const int ch  = idx & 15;
            const uint32_t d = s_base + swz2(row, ch << 4);
            cpa16(d,                 khiB + (size_t)row * Hdim + ch * 8);
            cpa16(d + TILE_HI_BYTES, kloB + (size_t)row * Hdim + ch * 8);
        }
        CP_COMMIT();
    }

    for (int kt = 0; kt < NTILE; ++kt) {
        CP_WAIT0();
        __syncthreads();   // tile kt visible; all warps done with the other buffer

        // ---- Prefetch tile kt+1 into the other buffer ----
        if (kt + 1 < NTILE) {
            const uint32_t sb = s_base + ((kt + 1) & 1) * TILE_BYTES;
            const __half* srcH = khiB + (size_t)(kt + 1) * BN * Hdim;
            const __half* srcL = kloB + (size_t)(kt + 1) * BN * Hdim;
            #pragma unroll
            for (int j = 0; j < 8; ++j) {
                const int idx = j * NT + t;
                const int row = idx >> 4;
                const int ch  = idx & 15;
                const uint32_t d = sb + swz2(row, ch << 4);
                cpa16(d,                 srcH + (size_t)row * Hdim + ch * 8);
                cpa16(d + TILE_HI_BYTES, srcL + (size_t)row * Hdim + ch * 8);
            }
            CP_COMMIT();
        }

        const uint32_t s_hi = s_base + (kt & 1) * TILE_BYTES;
        const uint32_t s_lo = s_hi + TILE_HI_BYTES;

        // =========== Phase 1: QK^T half A (keys 0..31) ===========
        float sa[4][4], sbv[4][4];
        #pragma unroll
        for (int n = 0; n < 4; ++n)
            #pragma unroll
            for (int j = 0; j < 4; ++j) { sa[n][j] = 0.f; sbv[n][j] = 0.f; }

        #pragma unroll
        for (int kk = 0; kk < 8; ++kk) {
            uint32_t bh[2][4], bl[2][4];
            #pragma unroll
            for (int np = 0; np < 2; ++np) {
                const int row = np * 16 + (lane & 7) + ((lane >> 4) << 3);
                const int col = kk * 32 + ((lane >> 3) & 1) * 16;   // bytes
                const uint32_t a = swz2(row, col);
                ldsm_x4(bh[np][0], bh[np][1], bh[np][2], bh[np][3], s_hi + a);
                ldsm_x4(bl[np][0], bl[np][1], bl[np][2], bl[np][3], s_lo + a);
            }
            #pragma unroll
            for (int n = 0; n < 4; ++n)
                mma16816(sa[n], qhi[kk], bh[n >> 1][(n & 1) * 2], bh[n >> 1][(n & 1) * 2 + 1]);
            #pragma unroll
            for (int n = 0; n < 4; ++n)
                mma16816(sa[n], qhi[kk], bl[n >> 1][(n & 1) * 2], bl[n >> 1][(n & 1) * 2 + 1]);
            #pragma unroll
            for (int n = 0; n < 4; ++n)
                mma16816(sa[n], qlo[kk], bh[n >> 1][(n & 1) * 2], bh[n >> 1][(n & 1) * 2 + 1]);
        }

        // =========== Phase 2: QK^T half B (keys 32..63), overlaps softmax A ===========
        #pragma unroll
        for (int kk = 0; kk < 8; ++kk) {
            uint32_t bh[2][4], bl[2][4];
            #pragma unroll
            for (int np = 0; np < 2; ++np) {
                const int row = (np + 2) * 16 + (lane & 7) + ((lane >> 4) << 3);
                const int col = kk * 32 + ((lane >> 3) & 1) * 16;
                const uint32_t a = swz2(row, col);
                ldsm_x4(bh[np][0], bh[np][1], bh[np][2], bh[np][3], s_hi + a);
                ldsm_x4(bl[np][0], bl[np][1], bl[np][2], bl[np][3], s_lo + a);
            }
            #pragma unroll
            for (int n = 0; n < 4; ++n)
                mma16816(sbv[n], qhi[kk], bh[n >> 1][(n & 1) * 2], bh[n >> 1][(n & 1) * 2 + 1]);
            #pragma unroll
            for (int n = 0; n < 4; ++n)
                mma16816(sbv[n], qhi[kk], bl[n >> 1][(n & 1) * 2], bl[n >> 1][(n & 1) * 2 + 1]);
            #pragma unroll
            for (int n = 0; n < 4; ++n)
                mma16816(sbv[n], qlo[kk], bh[n >> 1][(n & 1) * 2], bh[n >> 1][(n & 1) * 2 + 1]);
        }

        // ---- softmax A (independent of Phase 2 MMAs -> scheduler interleaves) ----
        uint32_t paA[2][4];
        float alA0, alA1;
        {
            float t0 = -INFINITY, t1 = -INFINITY;
            #pragma unroll
            for (int n = 0; n < 4; ++n) {
                t0 = fmaxf(t0, fmaxf(sa[n][0], sa[n][1]));
                t1 = fmaxf(t1, fmaxf(sa[n][2], sa[n][3]));
            }
            t0 = fmaxf(t0, __shfl_xor_sync(0xffffffffu, t0, 1));
            t0 = fmaxf(t0, __shfl_xor_sync(0xffffffffu, t0, 2));
            t1 = fmaxf(t1, __shfl_xor_sync(0xffffffffu, t1, 1));
            t1 = fmaxf(t1, __shfl_xor_sync(0xffffffffu, t1, 2));
            const float mn0 = fmaxf(m0, t0), mn1 = fmaxf(m1, t1);
            alA0 = __expf(m0 - mn0); alA1 = __expf(m1 - mn1);
            m0 = mn0; m1 = mn1;
            float rs0 = 0.f, rs1 = 0.f;
            #pragma unroll
            for (int n = 0; n < 4; ++n) {
                sa[n][0] = __expf(sa[n][0] - mn0);
                sa[n][1] = __expf(sa[n][1] - mn0);
                sa[n][2] = __expf(sa[n][2] - mn1);
                sa[n][3] = __expf(sa[n][3] - mn1);
                rs0 += sa[n][0] + sa[n][1];
                rs1 += sa[n][2] + sa[n][3];
            }
            rs0 += __shfl_xor_sync(0xffffffffu, rs0, 1);
            rs0 += __shfl_xor_sync(0xffffffffu, rs0, 2);
            rs1 += __shfl_xor_sync(0xffffffffu, rs1, 1);
            rs1 += __shfl_xor_sync(0xffffffffu, rs1, 2);
            l0 = l0 * alA0 + rs0;
            l1 = l1 * alA1 + rs1;
            #pragma unroll
            for (int kg = 0; kg < 2; ++kg) {
                paA[kg][0] = h2u(__floats2half2_rn(sa[2*kg][0],   sa[2*kg][1]));
                paA[kg][1] = h2u(__floats2half2_rn(sa[2*kg][2],   sa[2*kg][3]));
                paA[kg][2] = h2u(__floats2half2_rn(sa[2*kg+1][0], sa[2*kg+1][1]));
                paA[kg][3] = h2u(__floats2half2_rn(sa[2*kg+1][2], sa[2*kg+1][3]));
            }
        }

        // rescale O by alpha_A
        #pragma unroll
        for (int n = 0; n < 16; ++n) {
            o[n][0] *= alA0; o[n][1] *= alA0;
            o[n][2] *= alA1; o[n][3] *= alA1;
        }

        // =========== Phase 3: PV half A (key groups 0,1), overlaps softmax B ===========
        #pragma unroll
        for (int kg = 0; kg < 2; ++kg) {
            #pragma unroll
            for (int hp = 0; hp < 8; ++hp) {
                const int row = kg * 16 + (lane & 7) + (((lane >> 3) & 1) << 3);
                const int col = hp * 32 + ((lane >> 4) & 1) * 16;
                uint32_t r0, r1, r2, r3;
                ldsm_x4_t(r0, r1, r2, r3, s_hi + swz2(row, col));
                mma16816(o[2*hp],     paA[kg], r0, r1);
                mma16816(o[2*hp + 1], paA[kg], r2, r3);
            }
        }

        // ---- softmax B (independent of Phase 3 MMAs) ----
        uint32_t paB[2][4];
        float alB0, alB1;
        {
            float t0 = -INFINITY, t1 = -INFINITY;
            #pragma unroll
            for (int n = 0; n < 4; ++n) {
                t0 = fmaxf(t0, fmaxf(sbv[n][0], sbv[n][1]));
                t1 = fmaxf(t1, fmaxf(sbv[n][2], sbv[n][3]));
            }
            t0 = fmaxf(t0, __shfl_xor_sync(0xffffffffu, t0, 1));
            t0 = fmaxf(t0, __shfl_xor_sync(0xffffffffu, t0, 2));
            t1 = fmaxf(t1, __shfl_xor_sync(0xffffffffu, t1, 1));
            t1 = fmaxf(t1, __shfl_xor_sync(0xffffffffu, t1, 2));
            const float mn0 = fmaxf(m0, t0), mn1 = fmaxf(m1, t1);
            alB0 = __expf(m0 - mn0); alB1 = __expf(m1 - mn1);
            m0 = mn0; m1 = mn1;
            float rs0 = 0.f, rs1 = 0.f;
            #pragma unroll
            for (int n = 0; n < 4; ++n) {
                sbv[n][0] = __expf(sbv[n][0] - mn0);
                sbv[n][1] = __expf(sbv[n][1] - mn0);
                sbv[n][2] = __expf(sbv[n][2] - mn1);
                sbv[n][3] = __expf(sbv[n][3] - mn1);
                rs0 += sbv[n][0] + sbv[n][1];
                rs1 += sbv[n][2] + sbv[n][3];
            }
            rs0 += __shfl_xor_sync(0xffffffffu, rs0, 1);
            rs0 += __shfl_xor_sync(0xffffffffu, rs0, 2);
            rs1 += __shfl_xor_sync(0xffffffffu, rs1, 1);
            rs1 += __shfl_xor_sync(0xffffffffu, rs1, 2);
            l0 = l0 * alB0 + rs0;
            l1 = l1 * alB1 + rs1;
            #pragma unroll
            for (int kg = 0; kg < 2; ++kg) {
                paB[kg][0] = h2u(__floats2half2_rn(sbv[2*kg][0],   sbv[2*kg][1]));
                paB[kg][1] = h2u(__floats2half2_rn(sbv[2*kg][2],   sbv[2*kg][3]));
                paB[kg][2] = h2u(__floats2half2_rn(sbv[2*kg+1][0], sbv[2*kg+1][1]));
                paB[kg][3] = h2u(__floats2half2_rn(sbv[2*kg+1][2], sbv[2*kg+1][3]));
            }
        }

        // rescale O by alpha_B (PV_A contributions included — correct flash update)
        #pragma unroll
        for (int n = 0; n < 16; ++n) {
            o[n][0] *= alB0; o[n][1] *= alB0;
            o[n][2] *= alB1; o[n][3] *= alB1;
        }

        // =========== Phase 4: PV half B (key groups 2,3) ===========
        #pragma unroll
        for (int kg = 0; kg < 2; ++kg) {
            #pragma unroll
            for (int hp = 0; hp < 8; ++hp) {
                const int row = (kg + 2) * 16 + (lane & 7) + (((lane >> 3) & 1) << 3);
                const int col = hp * 32 + ((lane >> 4) & 1) * 16;
                uint32_t r0, r1, r2, r3;
                ldsm_x4_t(r0, r1, r2, r3, s_hi + swz2(row, col));
                mma16816(o[2*hp],     paB[kg], r0, r1);
                mma16816(o[2*hp + 1], paB[kg], r2, r3);
            }
        }
    }

    // ---- Epilogue: normalize and store ----
    const float inv0 = 1.0f / l0;
    const float inv1 = 1.0f / l1;
    float* ob = o_g + (size_t)(q0 + wm * 16 + g) * Hdim;
    #pragma unroll
    for (int n = 0; n < 16; ++n) {
        const int h = n * 8 + tc * 2;
        *(float2*)(ob + h)            = make_float2(o[n][0] * inv0, o[n][1] * inv0);
        *(float2*)(ob + 8 * Hdim + h) = make_float2(o[n][2] * inv1, o[n][3] * inv1);
    }
}

extern "C" void kernel_launch(void* const* d_in, const int* in_sizes, int n_in,
                              void* d_out, int out_size)
{
    const float* out_state = (const float*)d_in[0];
    const float* history   = (const float*)d_in[1];
    float*       out       = (float*)d_out;

    // 1) split history fp32 -> fp16 hi/lo scratch
    prep_split<<<KTOT / 8 / 256, 256>>>(history);

    // 2) fused flash attention on HMMA
    cudaFuncSetAttribute(attn_hmma, cudaFuncAttributeMaxDynamicSharedMemorySize, SMEM_BYTES);
    dim3 grid(Qlen / BM, Bsz);
    attn_hmma<<<grid, NT, SMEM_BYTES>>>(out_state, out);
}